// round 3
// baseline (speedup 1.0000x reference)
#include <cuda_runtime.h>

// Actor_Critic fused kernel — Round 0: fp32, fully fused, FFMA-bound design.
// 1 block = 32 batch rows (lane == row), 8 warps split output columns.
// All activations SMEM-resident; weights read via broadcast __ldg (L2-resident).

#define B_TOTAL 32768
#define M 32
#define STRIDE 1284          // floats per SMEM row; 1284/4=321 ≡ 1 (mod 32) -> conflict-free float4 LDS
#define SEG_A 0              // img_feat -> gated_fusion -> [query? no] -> attn -> (pol/val input)
#define SEG_B 256            // gated_att -> query -> pol1/val1
#define SEG_C 512            // _hx -> key -> pol2/val2
#define SEG_D 768            // _cx -> cx -> val_half -> attention_vector
#define SEG_E 1024           // hx
#define NTHREADS 256

#define OFF_VAL 0
#define OFF_POL (B_TOTAL)                       // 32768
#define OFF_HX  (B_TOTAL * 4)                   // 131072
#define OFF_CX  (B_TOTAL * 4 + B_TOTAL * 256)   // 8519680

struct P {
    const float *img, *hx0, *cx0, *query, *emb;
    const float *w_ta, *b_ta, *w_ih, *w_hh, *b_ih, *b_hh;
    const float *w_q, *b_q, *w_k, *b_k, *w_ba, *b_ba, *w_at, *b_at;
    const float *w_p1, *b_p1, *w_p2, *b_p2, *w_p, *b_p;
    const float *w_v1, *b_v1, *w_v2, *b_v2, *w_v, *b_v;
    const int *iidx;
    float *out;
};

__device__ __forceinline__ float sigm(float x) { return 1.0f / (1.0f + __expf(-x)); }
// NaN-safe tanh: exp overflow -> +inf -> 1-0 = 1; exp underflow -> 0 -> 1-2 = -1.
__device__ __forceinline__ float tanh_(float x) { return 1.0f - 2.0f / (__expf(2.0f * x) + 1.0f); }
__device__ __forceinline__ float relu_(float x) { return fmaxf(x, 0.0f); }

// acc[j] += sum_k xr[k] * w0[j*ldw + k], K multiple of 4.
// Per 4-k step: 1 LDS.128 (lane-varying row, conflict-free) + 8 broadcast LDG.128 + 32 FFMA.
template <int K>
__device__ __forceinline__ void accum8(float acc[8], const float* __restrict__ xr,
                                       const float* __restrict__ w0, int ldw) {
#pragma unroll 2
    for (int k = 0; k < K; k += 4) {
        float4 x = *(const float4*)(xr + k);
#pragma unroll
        for (int j = 0; j < 8; j++) {
            float4 w = __ldg((const float4*)(w0 + j * ldw + k));
            float a = acc[j];
            a = fmaf(x.x, w.x, a);
            a = fmaf(x.y, w.y, a);
            a = fmaf(x.z, w.z, a);
            a = fmaf(x.w, w.w, a);
            acc[j] = a;
        }
    }
}

extern "C" __global__ void __launch_bounds__(NTHREADS, 1)
actor_kernel(P p) {
    extern __shared__ float sm[];
    float* sx  = sm;                  // 32 x STRIDE activation tiles
    float* swe = sm + M * STRIDE;     // 32 x 28 embedding rows

    const int tid  = threadIdx.x;
    const int lane = tid & 31;
    const int warp = tid >> 5;
    const int row0 = blockIdx.x * M;

    // ---- Stage inputs: img_feat->A, _hx->C, _cx->D (coalesced float4) ----
    {
        const float4* gi = (const float4*)(p.img + (size_t)row0 * 256);
        const float4* gh = (const float4*)(p.hx0 + (size_t)row0 * 256);
        const float4* gc = (const float4*)(p.cx0 + (size_t)row0 * 256);
#pragma unroll
        for (int i = tid; i < M * 64; i += NTHREADS) {
            int r = i >> 6, c4 = (i & 63) << 2;
            *(float4*)(sx + r * STRIDE + SEG_A + c4) = gi[i];
            *(float4*)(sx + r * STRIDE + SEG_C + c4) = gh[i];
            *(float4*)(sx + r * STRIDE + SEG_D + c4) = gc[i];
        }
    }
    if (tid < M) {
        int idx = p.iidx[row0 + tid];
        const float* e = p.emb + idx * 25;
#pragma unroll
        for (int k = 0; k < 25; k++) swe[tid * 28 + k] = e[k];
    }
    __syncthreads();

    float* prow = sx + lane * STRIDE;

    // ---- G0: gated_att = sigmoid(we @ w_ta.T + b_ta); gated_fusion = img*ga ----
    {
        const float* xr = swe + lane * 28;
#pragma unroll 1
        for (int pass = 0; pass < 4; pass++) {
            int cb = pass * 64 + warp * 8;
            float acc[8] = {0, 0, 0, 0, 0, 0, 0, 0};
            for (int k = 0; k < 25; k++) {
                float xv = xr[k];
#pragma unroll
                for (int j = 0; j < 8; j++)
                    acc[j] = fmaf(xv, __ldg(p.w_ta + (cb + j) * 25 + k), acc[j]);
            }
#pragma unroll
            for (int j = 0; j < 8; j++) {
                int c = cb + j;
                float ga = sigm(acc[j] + __ldg(p.b_ta + c));
                prow[SEG_B + c] = ga;          // gated_att
                prow[SEG_A + c] *= ga;         // gated_fusion (exclusive per-thread slot)
            }
        }
    }
    __syncthreads();

    // ---- G1: LSTM gates (K=768 over [A,B | C]) + cell update ----
    // Per logical col c, accumulate the (i,f,g,o) quadruple = W rows {c, c+256, c+512, c+768}.
    {
#pragma unroll 1
        for (int pass = 0; pass < 16; pass++) {
            int cb = pass * 16 + warp * 2;     // two logical cols: cb, cb+1
            float acc[8] = {0, 0, 0, 0, 0, 0, 0, 0};   // acc[j*4+g]
#pragma unroll 2
            for (int k = 0; k < 512; k += 4) { // lstm_input part (A,B contiguous)
                float4 x = *(const float4*)(prow + k);
#pragma unroll
                for (int j = 0; j < 2; j++)
#pragma unroll
                    for (int g = 0; g < 4; g++) {
                        float4 w = __ldg((const float4*)(p.w_ih + ((size_t)((g << 8) + cb + j)) * 512 + k));
                        float a = acc[j * 4 + g];
                        a = fmaf(x.x, w.x, a); a = fmaf(x.y, w.y, a);
                        a = fmaf(x.z, w.z, a); a = fmaf(x.w, w.w, a);
                        acc[j * 4 + g] = a;
                    }
            }
#pragma unroll 2
            for (int k = 0; k < 256; k += 4) { // _hx part (C)
                float4 x = *(const float4*)(prow + SEG_C + k);
#pragma unroll
                for (int j = 0; j < 2; j++)
#pragma unroll
                    for (int g = 0; g < 4; g++) {
                        float4 w = __ldg((const float4*)(p.w_hh + ((size_t)((g << 8) + cb + j)) * 256 + k));
                        float a = acc[j * 4 + g];
                        a = fmaf(x.x, w.x, a); a = fmaf(x.y, w.y, a);
                        a = fmaf(x.z, w.z, a); a = fmaf(x.w, w.w, a);
                        acc[j * 4 + g] = a;
                    }
            }
#pragma unroll
            for (int j = 0; j < 2; j++) {
                int c = cb + j;
                float iv = sigm (acc[j * 4 + 0] + __ldg(p.b_ih + c)       + __ldg(p.b_hh + c));
                float fv = sigm (acc[j * 4 + 1] + __ldg(p.b_ih + 256 + c) + __ldg(p.b_hh + 256 + c));
                float gv = tanh_(acc[j * 4 + 2] + __ldg(p.b_ih + 512 + c) + __ldg(p.b_hh + 512 + c));
                float ov = sigm (acc[j * 4 + 3] + __ldg(p.b_ih + 768 + c) + __ldg(p.b_hh + 768 + c));
                float cxv = fv * prow[SEG_D + c] + iv * gv;  // in-place on _cx slot (exclusive)
                prow[SEG_D + c] = cxv;                        // cx
                prow[SEG_E + c] = ov * tanh_(cxv);            // hx
            }
        }
    }
    __syncthreads();

    // ---- Flush hx/cx to out; load query into B (gated_att dead) ----
    {
        float4* ghx = (float4*)(p.out + OFF_HX + (size_t)row0 * 256);
        float4* gcx = (float4*)(p.out + OFF_CX + (size_t)row0 * 256);
        const float4* gq = (const float4*)(p.query + (size_t)row0 * 256);
#pragma unroll
        for (int i = tid; i < M * 64; i += NTHREADS) {
            int r = i >> 6, c4 = (i & 63) << 2;
            ghx[i] = *(const float4*)(sx + r * STRIDE + SEG_E + c4);
            gcx[i] = *(const float4*)(sx + r * STRIDE + SEG_D + c4);
            *(float4*)(sx + r * STRIDE + SEG_B + c4) = gq[i];
        }
    }
    __syncthreads();

    // ---- G2: mlp_attn = relu([gated_fusion(A), hx(E)] @ w_ba.T + b_ba); key->C, val->D ----
    {
#pragma unroll 1
        for (int pass = 0; pass < 8; pass++) {
            int cb = pass * 64 + warp * 8;
            float acc[8] = {0, 0, 0, 0, 0, 0, 0, 0};
            accum8<256>(acc, prow + SEG_A, p.w_ba + (size_t)cb * 512,       512);
            accum8<256>(acc, prow + SEG_E, p.w_ba + (size_t)cb * 512 + 256, 512);
#pragma unroll
            for (int j = 0; j < 8; j++) {
                int c = cb + j;
                float v = relu_(acc[j] + __ldg(p.b_ba + c));
                if (c < 256) prow[SEG_C + c] = v;        // key_
                else         prow[SEG_D + c - 256] = v;  // val
            }
        }
    }
    __syncthreads();

    // ---- G3/G4: q_out=relu(query@w_q), k_out=relu(key@w_k); av = tanh(q+k)*val -> D ----
    {
#pragma unroll 1
        for (int pass = 0; pass < 4; pass++) {
            int cb = pass * 64 + warp * 8;
            float aq[8] = {0, 0, 0, 0, 0, 0, 0, 0};
            float ak[8] = {0, 0, 0, 0, 0, 0, 0, 0};
            accum8<256>(aq, prow + SEG_B, p.w_q + (size_t)cb * 256, 256);
            accum8<256>(ak, prow + SEG_C, p.w_k + (size_t)cb * 256, 256);
#pragma unroll
            for (int j = 0; j < 8; j++) {
                int c = cb + j;
                float qo = relu_(aq[j] + __ldg(p.b_q + c));
                float ko = relu_(ak[j] + __ldg(p.b_k + c));
                prow[SEG_D + c] = tanh_(qo + ko) * prow[SEG_D + c];  // in-place (exclusive)
            }
        }
    }
    __syncthreads();

    // ---- G5: attn = relu([av(D), hx(E)] @ w_at.T + b_at) -> A ----
    {
#pragma unroll 1
        for (int pass = 0; pass < 4; pass++) {
            int cb = pass * 64 + warp * 8;
            float acc[8] = {0, 0, 0, 0, 0, 0, 0, 0};
            accum8<256>(acc, prow + SEG_D, p.w_at + (size_t)cb * 512,       512);
            accum8<256>(acc, prow + SEG_E, p.w_at + (size_t)cb * 512 + 256, 512);
#pragma unroll
            for (int j = 0; j < 8; j++) {
                int c = cb + j;
                prow[SEG_A + c] = relu_(acc[j] + __ldg(p.b_at + c));
            }
        }
    }
    __syncthreads();

    // ---- G6: pol1 = relu(attn@w_p1) (128) -> B[0:128); G9: val1 = relu(attn@w_v1) (64) -> B[128:192) ----
    {
#pragma unroll 1
        for (int pass = 0; pass < 2; pass++) {
            int cb = pass * 64 + warp * 8;
            float acc[8] = {0, 0, 0, 0, 0, 0, 0, 0};
            accum8<256>(acc, prow + SEG_A, p.w_p1 + (size_t)cb * 256, 256);
#pragma unroll
            for (int j = 0; j < 8; j++)
                prow[SEG_B + cb + j] = relu_(acc[j] + __ldg(p.b_p1 + cb + j));
        }
        {
            int cb = warp * 8;
            float acc[8] = {0, 0, 0, 0, 0, 0, 0, 0};
            accum8<256>(acc, prow + SEG_A, p.w_v1 + (size_t)cb * 256, 256);
#pragma unroll
            for (int j = 0; j < 8; j++)
                prow[SEG_B + 128 + cb + j] = relu_(acc[j] + __ldg(p.b_v1 + cb + j));
        }
    }
    __syncthreads();

    // ---- G7: pol2 (64) -> C[0:64); G10: val2 (32) -> C[64:96) ----
    {
        {
            int cb = warp * 8;
            float acc[8] = {0, 0, 0, 0, 0, 0, 0, 0};
            accum8<128>(acc, prow + SEG_B, p.w_p2 + (size_t)cb * 128, 128);
#pragma unroll
            for (int j = 0; j < 8; j++)
                prow[SEG_C + cb + j] = relu_(acc[j] + __ldg(p.b_p2 + cb + j));
        }
        if (warp < 4) {
            int cb = warp * 8;
            float acc[8] = {0, 0, 0, 0, 0, 0, 0, 0};
            accum8<64>(acc, prow + SEG_B + 128, p.w_v2 + (size_t)cb * 64, 64);
#pragma unroll
            for (int j = 0; j < 8; j++)
                prow[SEG_C + 64 + cb + j] = relu_(acc[j] + __ldg(p.b_v2 + cb + j));
        }
    }
    __syncthreads();

    // ---- G8: pol = pol2 @ w_p.T + b_p (N=3, K=64); G11: val = val2 @ w_v.T + b_v (N=1, K=32) ----
    if (warp == 0) {
        float a0 = __ldg(p.b_p + 0), a1 = __ldg(p.b_p + 1), a2 = __ldg(p.b_p + 2);
#pragma unroll
        for (int k = 0; k < 64; k++) {
            float x = prow[SEG_C + k];
            a0 = fmaf(x, __ldg(p.w_p + k),       a0);
            a1 = fmaf(x, __ldg(p.w_p + 64 + k),  a1);
            a2 = fmaf(x, __ldg(p.w_p + 128 + k), a2);
        }
        float* po = p.out + OFF_POL + (size_t)(row0 + lane) * 3;
        po[0] = a0; po[1] = a1; po[2] = a2;
    } else if (warp == 1) {
        float a = __ldg(p.b_v);
#pragma unroll
        for (int k = 0; k < 32; k++)
            a = fmaf(prow[SEG_C + 64 + k], __ldg(p.w_v + k), a);
        p.out[OFF_VAL + row0 + lane] = a;
    }
}

extern "C" void kernel_launch(void* const* d_in, const int* in_sizes, int n_in,
                              void* d_out, int out_size) {
    P p;
    p.img   = (const float*)d_in[0];
    p.iidx  = (const int*)  d_in[1];
    p.hx0   = (const float*)d_in[2];
    p.cx0   = (const float*)d_in[3];
    p.query = (const float*)d_in[4];
    p.emb   = (const float*)d_in[5];
    p.w_ta  = (const float*)d_in[6];   p.b_ta = (const float*)d_in[7];
    p.w_ih  = (const float*)d_in[8];   p.w_hh = (const float*)d_in[9];
    p.b_ih  = (const float*)d_in[10];  p.b_hh = (const float*)d_in[11];
    p.w_q   = (const float*)d_in[12];  p.b_q  = (const float*)d_in[13];
    p.w_k   = (const float*)d_in[14];  p.b_k  = (const float*)d_in[15];
    p.w_ba  = (const float*)d_in[16];  p.b_ba = (const float*)d_in[17];
    p.w_at  = (const float*)d_in[18];  p.b_at = (const float*)d_in[19];
    p.w_p1  = (const float*)d_in[20];  p.b_p1 = (const float*)d_in[21];
    p.w_p2  = (const float*)d_in[22];  p.b_p2 = (const float*)d_in[23];
    p.w_p   = (const float*)d_in[24];  p.b_p  = (const float*)d_in[25];
    p.w_v1  = (const float*)d_in[26];  p.b_v1 = (const float*)d_in[27];
    p.w_v2  = (const float*)d_in[28];  p.b_v2 = (const float*)d_in[29];
    p.w_v   = (const float*)d_in[30];  p.b_v  = (const float*)d_in[31];
    p.out   = (float*)d_out;

    size_t smem = (size_t)(M * STRIDE + M * 28) * sizeof(float);  // ~168 KB
    cudaFuncSetAttribute(actor_kernel, cudaFuncAttributeMaxDynamicSharedMemorySize, (int)smem);
    actor_kernel<<<B_TOTAL / M, NTHREADS, smem>>>(p);
}

// round 4
// speedup vs baseline: 1.0006x; 1.0006x over previous
#include <cuda_runtime.h>

// Actor_Critic fused kernel — Round 0: fp32, fully fused, FFMA-bound design.
// 1 block = 32 batch rows (lane == row), 8 warps split output columns.
// All activations SMEM-resident; weights read via broadcast __ldg (L2-resident).

#define B_TOTAL 32768
#define M 32
#define STRIDE 1284          // floats per SMEM row; 1284/4=321 ≡ 1 (mod 32) -> conflict-free float4 LDS
#define SEG_A 0              // img_feat -> gated_fusion -> [query? no] -> attn -> (pol/val input)
#define SEG_B 256            // gated_att -> query -> pol1/val1
#define SEG_C 512            // _hx -> key -> pol2/val2
#define SEG_D 768            // _cx -> cx -> val_half -> attention_vector
#define SEG_E 1024           // hx
#define NTHREADS 256

#define OFF_VAL 0
#define OFF_POL (B_TOTAL)                       // 32768
#define OFF_HX  (B_TOTAL * 4)                   // 131072
#define OFF_CX  (B_TOTAL * 4 + B_TOTAL * 256)   // 8519680

struct P {
    const float *img, *hx0, *cx0, *query, *emb;
    const float *w_ta, *b_ta, *w_ih, *w_hh, *b_ih, *b_hh;
    const float *w_q, *b_q, *w_k, *b_k, *w_ba, *b_ba, *w_at, *b_at;
    const float *w_p1, *b_p1, *w_p2, *b_p2, *w_p, *b_p;
    const float *w_v1, *b_v1, *w_v2, *b_v2, *w_v, *b_v;
    const int *iidx;
    float *out;
};

__device__ __forceinline__ float sigm(float x) { return 1.0f / (1.0f + __expf(-x)); }
// NaN-safe tanh: exp overflow -> +inf -> 1-0 = 1; exp underflow -> 0 -> 1-2 = -1.
__device__ __forceinline__ float tanh_(float x) { return 1.0f - 2.0f / (__expf(2.0f * x) + 1.0f); }
__device__ __forceinline__ float relu_(float x) { return fmaxf(x, 0.0f); }

// acc[j] += sum_k xr[k] * w0[j*ldw + k], K multiple of 4.
// Per 4-k step: 1 LDS.128 (lane-varying row, conflict-free) + 8 broadcast LDG.128 + 32 FFMA.
template <int K>
__device__ __forceinline__ void accum8(float acc[8], const float* __restrict__ xr,
                                       const float* __restrict__ w0, int ldw) {
#pragma unroll 2
    for (int k = 0; k < K; k += 4) {
        float4 x = *(const float4*)(xr + k);
#pragma unroll
        for (int j = 0; j < 8; j++) {
            float4 w = __ldg((const float4*)(w0 + j * ldw + k));
            float a = acc[j];
            a = fmaf(x.x, w.x, a);
            a = fmaf(x.y, w.y, a);
            a = fmaf(x.z, w.z, a);
            a = fmaf(x.w, w.w, a);
            acc[j] = a;
        }
    }
}

extern "C" __global__ void __launch_bounds__(NTHREADS, 1)
actor_kernel(P p) {
    extern __shared__ float sm[];
    float* sx  = sm;                  // 32 x STRIDE activation tiles
    float* swe = sm + M * STRIDE;     // 32 x 28 embedding rows

    const int tid  = threadIdx.x;
    const int lane = tid & 31;
    const int warp = tid >> 5;
    const int row0 = blockIdx.x * M;

    // ---- Stage inputs: img_feat->A, _hx->C, _cx->D (coalesced float4) ----
    {
        const float4* gi = (const float4*)(p.img + (size_t)row0 * 256);
        const float4* gh = (const float4*)(p.hx0 + (size_t)row0 * 256);
        const float4* gc = (const float4*)(p.cx0 + (size_t)row0 * 256);
#pragma unroll
        for (int i = tid; i < M * 64; i += NTHREADS) {
            int r = i >> 6, c4 = (i & 63) << 2;
            *(float4*)(sx + r * STRIDE + SEG_A + c4) = gi[i];
            *(float4*)(sx + r * STRIDE + SEG_C + c4) = gh[i];
            *(float4*)(sx + r * STRIDE + SEG_D + c4) = gc[i];
        }
    }
    if (tid < M) {
        int idx = p.iidx[row0 + tid];
        const float* e = p.emb + idx * 25;
#pragma unroll
        for (int k = 0; k < 25; k++) swe[tid * 28 + k] = e[k];
    }
    __syncthreads();

    float* prow = sx + lane * STRIDE;

    // ---- G0: gated_att = sigmoid(we @ w_ta.T + b_ta); gated_fusion = img*ga ----
    {
        const float* xr = swe + lane * 28;
#pragma unroll 1
        for (int pass = 0; pass < 4; pass++) {
            int cb = pass * 64 + warp * 8;
            float acc[8] = {0, 0, 0, 0, 0, 0, 0, 0};
            for (int k = 0; k < 25; k++) {
                float xv = xr[k];
#pragma unroll
                for (int j = 0; j < 8; j++)
                    acc[j] = fmaf(xv, __ldg(p.w_ta + (cb + j) * 25 + k), acc[j]);
            }
#pragma unroll
            for (int j = 0; j < 8; j++) {
                int c = cb + j;
                float ga = sigm(acc[j] + __ldg(p.b_ta + c));
                prow[SEG_B + c] = ga;          // gated_att
                prow[SEG_A + c] *= ga;         // gated_fusion (exclusive per-thread slot)
            }
        }
    }
    __syncthreads();

    // ---- G1: LSTM gates (K=768 over [A,B | C]) + cell update ----
    // Per logical col c, accumulate the (i,f,g,o) quadruple = W rows {c, c+256, c+512, c+768}.
    {
#pragma unroll 1
        for (int pass = 0; pass < 16; pass++) {
            int cb = pass * 16 + warp * 2;     // two logical cols: cb, cb+1
            float acc[8] = {0, 0, 0, 0, 0, 0, 0, 0};   // acc[j*4+g]
#pragma unroll 2
            for (int k = 0; k < 512; k += 4) { // lstm_input part (A,B contiguous)
                float4 x = *(const float4*)(prow + k);
#pragma unroll
                for (int j = 0; j < 2; j++)
#pragma unroll
                    for (int g = 0; g < 4; g++) {
                        float4 w = __ldg((const float4*)(p.w_ih + ((size_t)((g << 8) + cb + j)) * 512 + k));
                        float a = acc[j * 4 + g];
                        a = fmaf(x.x, w.x, a); a = fmaf(x.y, w.y, a);
                        a = fmaf(x.z, w.z, a); a = fmaf(x.w, w.w, a);
                        acc[j * 4 + g] = a;
                    }
            }
#pragma unroll 2
            for (int k = 0; k < 256; k += 4) { // _hx part (C)
                float4 x = *(const float4*)(prow + SEG_C + k);
#pragma unroll
                for (int j = 0; j < 2; j++)
#pragma unroll
                    for (int g = 0; g < 4; g++) {
                        float4 w = __ldg((const float4*)(p.w_hh + ((size_t)((g << 8) + cb + j)) * 256 + k));
                        float a = acc[j * 4 + g];
                        a = fmaf(x.x, w.x, a); a = fmaf(x.y, w.y, a);
                        a = fmaf(x.z, w.z, a); a = fmaf(x.w, w.w, a);
                        acc[j * 4 + g] = a;
                    }
            }
#pragma unroll
            for (int j = 0; j < 2; j++) {
                int c = cb + j;
                float iv = sigm (acc[j * 4 + 0] + __ldg(p.b_ih + c)       + __ldg(p.b_hh + c));
                float fv = sigm (acc[j * 4 + 1] + __ldg(p.b_ih + 256 + c) + __ldg(p.b_hh + 256 + c));
                float gv = tanh_(acc[j * 4 + 2] + __ldg(p.b_ih + 512 + c) + __ldg(p.b_hh + 512 + c));
                float ov = sigm (acc[j * 4 + 3] + __ldg(p.b_ih + 768 + c) + __ldg(p.b_hh + 768 + c));
                float cxv = fv * prow[SEG_D + c] + iv * gv;  // in-place on _cx slot (exclusive)
                prow[SEG_D + c] = cxv;                        // cx
                prow[SEG_E + c] = ov * tanh_(cxv);            // hx
            }
        }
    }
    __syncthreads();

    // ---- Flush hx/cx to out; load query into B (gated_att dead) ----
    {
        float4* ghx = (float4*)(p.out + OFF_HX + (size_t)row0 * 256);
        float4* gcx = (float4*)(p.out + OFF_CX + (size_t)row0 * 256);
        const float4* gq = (const float4*)(p.query + (size_t)row0 * 256);
#pragma unroll
        for (int i = tid; i < M * 64; i += NTHREADS) {
            int r = i >> 6, c4 = (i & 63) << 2;
            ghx[i] = *(const float4*)(sx + r * STRIDE + SEG_E + c4);
            gcx[i] = *(const float4*)(sx + r * STRIDE + SEG_D + c4);
            *(float4*)(sx + r * STRIDE + SEG_B + c4) = gq[i];
        }
    }
    __syncthreads();

    // ---- G2: mlp_attn = relu([gated_fusion(A), hx(E)] @ w_ba.T + b_ba); key->C, val->D ----
    {
#pragma unroll 1
        for (int pass = 0; pass < 8; pass++) {
            int cb = pass * 64 + warp * 8;
            float acc[8] = {0, 0, 0, 0, 0, 0, 0, 0};
            accum8<256>(acc, prow + SEG_A, p.w_ba + (size_t)cb * 512,       512);
            accum8<256>(acc, prow + SEG_E, p.w_ba + (size_t)cb * 512 + 256, 512);
#pragma unroll
            for (int j = 0; j < 8; j++) {
                int c = cb + j;
                float v = relu_(acc[j] + __ldg(p.b_ba + c));
                if (c < 256) prow[SEG_C + c] = v;        // key_
                else         prow[SEG_D + c - 256] = v;  // val
            }
        }
    }
    __syncthreads();

    // ---- G3/G4: q_out=relu(query@w_q), k_out=relu(key@w_k); av = tanh(q+k)*val -> D ----
    {
#pragma unroll 1
        for (int pass = 0; pass < 4; pass++) {
            int cb = pass * 64 + warp * 8;
            float aq[8] = {0, 0, 0, 0, 0, 0, 0, 0};
            float ak[8] = {0, 0, 0, 0, 0, 0, 0, 0};
            accum8<256>(aq, prow + SEG_B, p.w_q + (size_t)cb * 256, 256);
            accum8<256>(ak, prow + SEG_C, p.w_k + (size_t)cb * 256, 256);
#pragma unroll
            for (int j = 0; j < 8; j++) {
                int c = cb + j;
                float qo = relu_(aq[j] + __ldg(p.b_q + c));
                float ko = relu_(ak[j] + __ldg(p.b_k + c));
                prow[SEG_D + c] = tanh_(qo + ko) * prow[SEG_D + c];  // in-place (exclusive)
            }
        }
    }
    __syncthreads();

    // ---- G5: attn = relu([av(D), hx(E)] @ w_at.T + b_at) -> A ----
    {
#pragma unroll 1
        for (int pass = 0; pass < 4; pass++) {
            int cb = pass * 64 + warp * 8;
            float acc[8] = {0, 0, 0, 0, 0, 0, 0, 0};
            accum8<256>(acc, prow + SEG_D, p.w_at + (size_t)cb * 512,       512);
            accum8<256>(acc, prow + SEG_E, p.w_at + (size_t)cb * 512 + 256, 512);
#pragma unroll
            for (int j = 0; j < 8; j++) {
                int c = cb + j;
                prow[SEG_A + c] = relu_(acc[j] + __ldg(p.b_at + c));
            }
        }
    }
    __syncthreads();

    // ---- G6: pol1 = relu(attn@w_p1) (128) -> B[0:128); G9: val1 = relu(attn@w_v1) (64) -> B[128:192) ----
    {
#pragma unroll 1
        for (int pass = 0; pass < 2; pass++) {
            int cb = pass * 64 + warp * 8;
            float acc[8] = {0, 0, 0, 0, 0, 0, 0, 0};
            accum8<256>(acc, prow + SEG_A, p.w_p1 + (size_t)cb * 256, 256);
#pragma unroll
            for (int j = 0; j < 8; j++)
                prow[SEG_B + cb + j] = relu_(acc[j] + __ldg(p.b_p1 + cb + j));
        }
        {
            int cb = warp * 8;
            float acc[8] = {0, 0, 0, 0, 0, 0, 0, 0};
            accum8<256>(acc, prow + SEG_A, p.w_v1 + (size_t)cb * 256, 256);
#pragma unroll
            for (int j = 0; j < 8; j++)
                prow[SEG_B + 128 + cb + j] = relu_(acc[j] + __ldg(p.b_v1 + cb + j));
        }
    }
    __syncthreads();

    // ---- G7: pol2 (64) -> C[0:64); G10: val2 (32) -> C[64:96) ----
    {
        {
            int cb = warp * 8;
            float acc[8] = {0, 0, 0, 0, 0, 0, 0, 0};
            accum8<128>(acc, prow + SEG_B, p.w_p2 + (size_t)cb * 128, 128);
#pragma unroll
            for (int j = 0; j < 8; j++)
                prow[SEG_C + cb + j] = relu_(acc[j] + __ldg(p.b_p2 + cb + j));
        }
        if (warp < 4) {
            int cb = warp * 8;
            float acc[8] = {0, 0, 0, 0, 0, 0, 0, 0};
            accum8<64>(acc, prow + SEG_B + 128, p.w_v2 + (size_t)cb * 64, 64);
#pragma unroll
            for (int j = 0; j < 8; j++)
                prow[SEG_C + 64 + cb + j] = relu_(acc[j] + __ldg(p.b_v2 + cb + j));
        }
    }
    __syncthreads();

    // ---- G8: pol = pol2 @ w_p.T + b_p (N=3, K=64); G11: val = val2 @ w_v.T + b_v (N=1, K=32) ----
    if (warp == 0) {
        float a0 = __ldg(p.b_p + 0), a1 = __ldg(p.b_p + 1), a2 = __ldg(p.b_p + 2);
#pragma unroll
        for (int k = 0; k < 64; k++) {
            float x = prow[SEG_C + k];
            a0 = fmaf(x, __ldg(p.w_p + k),       a0);
            a1 = fmaf(x, __ldg(p.w_p + 64 + k),  a1);
            a2 = fmaf(x, __ldg(p.w_p + 128 + k), a2);
        }
        float* po = p.out + OFF_POL + (size_t)(row0 + lane) * 3;
        po[0] = a0; po[1] = a1; po[2] = a2;
    } else if (warp == 1) {
        float a = __ldg(p.b_v);
#pragma unroll
        for (int k = 0; k < 32; k++)
            a = fmaf(prow[SEG_C + 64 + k], __ldg(p.w_v + k), a);
        p.out[OFF_VAL + row0 + lane] = a;
    }
}

extern "C" void kernel_launch(void* const* d_in, const int* in_sizes, int n_in,
                              void* d_out, int out_size) {
    P p;
    p.img   = (const float*)d_in[0];
    p.iidx  = (const int*)  d_in[1];
    p.hx0   = (const float*)d_in[2];
    p.cx0   = (const float*)d_in[3];
    p.query = (const float*)d_in[4];
    p.emb   = (const float*)d_in[5];
    p.w_ta  = (const float*)d_in[6];   p.b_ta = (const float*)d_in[7];
    p.w_ih  = (const float*)d_in[8];   p.w_hh = (const float*)d_in[9];
    p.b_ih  = (const float*)d_in[10];  p.b_hh = (const float*)d_in[11];
    p.w_q   = (const float*)d_in[12];  p.b_q  = (const float*)d_in[13];
    p.w_k   = (const float*)d_in[14];  p.b_k  = (const float*)d_in[15];
    p.w_ba  = (const float*)d_in[16];  p.b_ba = (const float*)d_in[17];
    p.w_at  = (const float*)d_in[18];  p.b_at = (const float*)d_in[19];
    p.w_p1  = (const float*)d_in[20];  p.b_p1 = (const float*)d_in[21];
    p.w_p2  = (const float*)d_in[22];  p.b_p2 = (const float*)d_in[23];
    p.w_p   = (const float*)d_in[24];  p.b_p  = (const float*)d_in[25];
    p.w_v1  = (const float*)d_in[26];  p.b_v1 = (const float*)d_in[27];
    p.w_v2  = (const float*)d_in[28];  p.b_v2 = (const float*)d_in[29];
    p.w_v   = (const float*)d_in[30];  p.b_v  = (const float*)d_in[31];
    p.out   = (float*)d_out;

    size_t smem = (size_t)(M * STRIDE + M * 28) * sizeof(float);  // ~168 KB
    cudaFuncSetAttribute(actor_kernel, cudaFuncAttributeMaxDynamicSharedMemorySize, (int)smem);
    actor_kernel<<<B_TOTAL / M, NTHREADS, smem>>>(p);
}

// round 5
// speedup vs baseline: 1.5214x; 1.5205x over previous
#include <cuda_runtime.h>

// Actor_Critic fused kernel — Round 5: fp32 FFMA2 (f32x2 K-pair), M=64 rows/block.
// 3 SMEM segments (S0,S1,S2), cx via gmem, hx via out-roundtrip, val/av via
// col-major __device__ scratch. 256 threads, each thread owns rows (lane, lane+32).

#define B_TOTAL 32768
#define M 64
#define STRIDE 772           // 3*256+4 floats; float4-stride 193 (odd) -> conflict-free
#define NTHREADS 256
#define S0 0
#define S1 256
#define S2 512

#define OFF_VAL 0
#define OFF_POL (B_TOTAL)
#define OFF_HX  (B_TOTAL * 4)
#define OFF_CX  (B_TOTAL * 4 + B_TOTAL * 256)

typedef unsigned long long u64;

// column-major scratch: g_val[c * B_TOTAL + row]  (lane=row -> coalesced)
__device__ float g_val[(size_t)256 * B_TOTAL];

struct P {
    const float *img, *hx0, *cx0, *query, *emb;
    const float *w_ta, *b_ta, *w_ih, *w_hh, *b_ih, *b_hh;
    const float *w_q, *b_q, *w_k, *b_k, *w_ba, *b_ba, *w_at, *b_at;
    const float *w_p1, *b_p1, *w_p2, *b_p2, *w_p, *b_p;
    const float *w_v1, *b_v1, *w_v2, *b_v2, *w_v, *b_v;
    const int *iidx;
    float *out;
};

__device__ __forceinline__ void fma2(u64 &d, u64 a, u64 b) {
    asm("fma.rn.f32x2 %0, %1, %2, %0;" : "+l"(d) : "l"(a), "l"(b));
}
__device__ __forceinline__ float red2(u64 a) {
    return __uint_as_float((unsigned)a) + __uint_as_float((unsigned)(a >> 32));
}
__device__ __forceinline__ float sigm(float x) { return 1.0f / (1.0f + __expf(-x)); }
// NaN-safe tanh
__device__ __forceinline__ float tanh_(float x) { return 1.0f - 2.0f / (__expf(2.0f * x) + 1.0f); }
__device__ __forceinline__ float relu_(float x) { return fmaxf(x, 0.0f); }

// acc{A,B}[j] (f32x2 even/odd-k partials) += x_{a,b}[k] * w0[j*ldw + k], K % 4 == 0.
// Per 4-k step: 2 LDS.128 + 8 LDG.128 + 32 FFMA2 = 2048 MACs.
template <int K>
__device__ __forceinline__ void accum8x2(u64 aA[8], u64 aB[8],
                                         const float* __restrict__ xa,
                                         const float* __restrict__ xb,
                                         const float* __restrict__ w0, int ldw) {
#pragma unroll 2
    for (int k = 0; k < K; k += 4) {
        ulonglong2 x0 = *(const ulonglong2*)(xa + k);
        ulonglong2 x1 = *(const ulonglong2*)(xb + k);
#pragma unroll
        for (int j = 0; j < 8; j++) {
            ulonglong2 w = __ldg((const ulonglong2*)(w0 + (size_t)j * ldw + k));
            fma2(aA[j], x0.x, w.x); fma2(aA[j], x0.y, w.y);
            fma2(aB[j], x1.x, w.x); fma2(aB[j], x1.y, w.y);
        }
    }
}

extern "C" __global__ void __launch_bounds__(NTHREADS, 1)
actor_kernel(P p) {
    extern __shared__ float sm[];
    float* sx  = sm;                  // 64 x STRIDE activation tiles
    float* swe = sm + M * STRIDE;     // 64 x 28 embedding rows

    const int tid  = threadIdx.x;
    const int lane = tid & 31;
    const int warp = tid >> 5;
    const int row0 = blockIdx.x * M;

    // ---- Stage inputs: img->S0, hx_in->S2 ----
    {
        const float4* gi = (const float4*)(p.img + (size_t)row0 * 256);
        const float4* gh = (const float4*)(p.hx0 + (size_t)row0 * 256);
#pragma unroll
        for (int i = tid; i < M * 64; i += NTHREADS) {
            int r = i >> 6, c4 = (i & 63) << 2;
            *(float4*)(sx + r * STRIDE + S0 + c4) = gi[i];
            *(float4*)(sx + r * STRIDE + S2 + c4) = gh[i];
        }
    }
    if (tid < M) {
        int idx = p.iidx[row0 + tid];
        const float* e = p.emb + idx * 25;
#pragma unroll
        for (int k = 0; k < 25; k++) swe[tid * 28 + k] = e[k];
    }
    __syncthreads();

    float* prow_a = sx + lane * STRIDE;
    float* prow_b = prow_a + 32 * STRIDE;

    // ---- G0: gated_att = sigmoid(we @ w_ta.T + b_ta) -> S1; gated_fusion = img*ga -> S0 ----
    {
#pragma unroll 1
        for (int pass = 0; pass < 4; pass++) {
            int cb = pass * 64 + warp * 8;
            float a0[8] = {0,0,0,0,0,0,0,0}, a1[8] = {0,0,0,0,0,0,0,0};
            for (int k = 0; k < 25; k++) {
                float xa = swe[lane * 28 + k], xb = swe[(lane + 32) * 28 + k];
#pragma unroll
                for (int j = 0; j < 8; j++) {
                    float w = __ldg(p.w_ta + (cb + j) * 25 + k);
                    a0[j] = fmaf(xa, w, a0[j]);
                    a1[j] = fmaf(xb, w, a1[j]);
                }
            }
#pragma unroll
            for (int j = 0; j < 8; j++) {
                int c = cb + j;
                float b = __ldg(p.b_ta + c);
                float gA = sigm(a0[j] + b), gB = sigm(a1[j] + b);
                prow_a[S1 + c] = gA;  prow_a[S0 + c] *= gA;
                prow_b[S1 + c] = gB;  prow_b[S0 + c] *= gB;
            }
        }
    }
    __syncthreads();

    // ---- G1: LSTM. K=768 contiguous [gf|ga|hx]; gate quad per logical col. ----
    {
#pragma unroll 1
        for (int pass = 0; pass < 16; pass++) {
            int c0 = pass * 16 + warp * 2;     // even -> float2-aligned col pair
            u64 aA[8] = {0,0,0,0,0,0,0,0};     // [j*4+g] rows lane
            u64 aB[8] = {0,0,0,0,0,0,0,0};     // rows lane+32
#pragma unroll 2
            for (int k = 0; k < 512; k += 4) {
                ulonglong2 x0 = *(const ulonglong2*)(prow_a + k);
                ulonglong2 x1 = *(const ulonglong2*)(prow_b + k);
#pragma unroll
                for (int j = 0; j < 2; j++)
#pragma unroll
                    for (int g = 0; g < 4; g++) {
                        ulonglong2 w = __ldg((const ulonglong2*)(p.w_ih + (size_t)((g << 8) + c0 + j) * 512 + k));
                        fma2(aA[j*4+g], x0.x, w.x); fma2(aA[j*4+g], x0.y, w.y);
                        fma2(aB[j*4+g], x1.x, w.x); fma2(aB[j*4+g], x1.y, w.y);
                    }
            }
#pragma unroll 2
            for (int k = 0; k < 256; k += 4) {
                ulonglong2 x0 = *(const ulonglong2*)(prow_a + S2 + k);
                ulonglong2 x1 = *(const ulonglong2*)(prow_b + S2 + k);
#pragma unroll
                for (int j = 0; j < 2; j++)
#pragma unroll
                    for (int g = 0; g < 4; g++) {
                        ulonglong2 w = __ldg((const ulonglong2*)(p.w_hh + (size_t)((g << 8) + c0 + j) * 256 + k));
                        fma2(aA[j*4+g], x0.x, w.x); fma2(aA[j*4+g], x0.y, w.y);
                        fma2(aB[j*4+g], x1.x, w.x); fma2(aB[j*4+g], x1.y, w.y);
                    }
            }
            // Epilogue: cell update; hx/cx -> out (float2 col-pair stores)
            float bI0 = __ldg(p.b_ih + c0)       + __ldg(p.b_hh + c0);
            float bI1 = __ldg(p.b_ih + c0 + 1)   + __ldg(p.b_hh + c0 + 1);
            float bF0 = __ldg(p.b_ih + 256 + c0)     + __ldg(p.b_hh + 256 + c0);
            float bF1 = __ldg(p.b_ih + 256 + c0 + 1) + __ldg(p.b_hh + 256 + c0 + 1);
            float bG0 = __ldg(p.b_ih + 512 + c0)     + __ldg(p.b_hh + 512 + c0);
            float bG1 = __ldg(p.b_ih + 512 + c0 + 1) + __ldg(p.b_hh + 512 + c0 + 1);
            float bO0 = __ldg(p.b_ih + 768 + c0)     + __ldg(p.b_hh + 768 + c0);
            float bO1 = __ldg(p.b_ih + 768 + c0 + 1) + __ldg(p.b_hh + 768 + c0 + 1);
#pragma unroll
            for (int r = 0; r < 2; r++) {
                int row = row0 + lane + r * 32;
                float2 cxin = __ldg((const float2*)(p.cx0 + (size_t)row * 256 + c0));
                float i0 = sigm ((r ? red2(aB[0]) : red2(aA[0])) + bI0);
                float f0 = sigm ((r ? red2(aB[1]) : red2(aA[1])) + bF0);
                float g0 = tanh_((r ? red2(aB[2]) : red2(aA[2])) + bG0);
                float o0 = sigm ((r ? red2(aB[3]) : red2(aA[3])) + bO0);
                float i1 = sigm ((r ? red2(aB[4]) : red2(aA[4])) + bI1);
                float f1 = sigm ((r ? red2(aB[5]) : red2(aA[5])) + bF1);
                float g1 = tanh_((r ? red2(aB[6]) : red2(aA[6])) + bG1);
                float o1 = sigm ((r ? red2(aB[7]) : red2(aA[7])) + bO1);
                float2 cxo, hxo;
                cxo.x = f0 * cxin.x + i0 * g0;  hxo.x = o0 * tanh_(cxo.x);
                cxo.y = f1 * cxin.y + i1 * g1;  hxo.y = o1 * tanh_(cxo.y);
                *(float2*)(p.out + OFF_CX + (size_t)row * 256 + c0) = cxo;
                *(float2*)(p.out + OFF_HX + (size_t)row * 256 + c0) = hxo;
            }
        }
    }
    __syncthreads();   // all hx STGs visible block-wide

    // ---- Reload hx from out -> S2 (overwrite hx_in) ----
    {
        const float4* gh = (const float4*)(p.out + OFF_HX + (size_t)row0 * 256);
#pragma unroll
        for (int i = tid; i < M * 64; i += NTHREADS) {
            int r = i >> 6, c4 = (i & 63) << 2;
            *(float4*)(sx + r * STRIDE + S2 + c4) = gh[i];
        }
    }
    __syncthreads();

    // ---- G2: mlp_attn = relu([gf(S0) | hx(S2)] @ w_ba.T + b_ba); key->S1, val->scratch ----
    {
#pragma unroll 1
        for (int pass = 0; pass < 8; pass++) {
            int cb = pass * 64 + warp * 8;
            u64 aA[8] = {0,0,0,0,0,0,0,0}, aB[8] = {0,0,0,0,0,0,0,0};
            accum8x2<256>(aA, aB, prow_a + S0, prow_b + S0, p.w_ba + (size_t)cb * 512,       512);
            accum8x2<256>(aA, aB, prow_a + S2, prow_b + S2, p.w_ba + (size_t)cb * 512 + 256, 512);
#pragma unroll
            for (int j = 0; j < 8; j++) {
                int c = cb + j;
                float b = __ldg(p.b_ba + c);
                float vA = relu_(red2(aA[j]) + b), vB = relu_(red2(aB[j]) + b);
                if (c < 256) { prow_a[S1 + c] = vA; prow_b[S1 + c] = vB; }
                else {
                    size_t ib = (size_t)(c - 256) * B_TOTAL + row0 + lane;
                    g_val[ib] = vA; g_val[ib + 32] = vB;
                }
            }
        }
    }
    __syncthreads();   // key visible; S0 free

    // ---- Load query -> S0 ----
    {
        const float4* gq = (const float4*)(p.query + (size_t)row0 * 256);
#pragma unroll
        for (int i = tid; i < M * 64; i += NTHREADS) {
            int r = i >> 6, c4 = (i & 63) << 2;
            *(float4*)(sx + r * STRIDE + S0 + c4) = gq[i];
        }
    }
    __syncthreads();

    // ---- G3/G4: q=relu(query@w_q), k=relu(key@w_k); av = tanh(q+k)*val -> scratch ----
    {
#pragma unroll 1
        for (int pass = 0; pass < 4; pass++) {
            int cb = pass * 64 + warp * 8;
            u64 aA[8] = {0,0,0,0,0,0,0,0}, aB[8] = {0,0,0,0,0,0,0,0};
            accum8x2<256>(aA, aB, prow_a + S0, prow_b + S0, p.w_q + (size_t)cb * 256, 256);
            float qA[8], qB[8];
#pragma unroll
            for (int j = 0; j < 8; j++) {
                float b = __ldg(p.b_q + cb + j);
                qA[j] = relu_(red2(aA[j]) + b);
                qB[j] = relu_(red2(aB[j]) + b);
            }
            u64 kA[8] = {0,0,0,0,0,0,0,0}, kB[8] = {0,0,0,0,0,0,0,0};
            accum8x2<256>(kA, kB, prow_a + S1, prow_b + S1, p.w_k + (size_t)cb * 256, 256);
#pragma unroll
            for (int j = 0; j < 8; j++) {
                int c = cb + j;
                float b = __ldg(p.b_k + c);
                float koA = relu_(red2(kA[j]) + b), koB = relu_(red2(kB[j]) + b);
                size_t ib = (size_t)c * B_TOTAL + row0 + lane;
                float avA = tanh_(qA[j] + koA) * g_val[ib];
                float avB = tanh_(qB[j] + koB) * g_val[ib + 32];
                g_val[ib] = avA; g_val[ib + 32] = avB;
            }
        }
    }
    __syncthreads();

    // ---- av scratch -> S1 (coalesced over rows) ----
    for (int c = warp; c < 256; c += 8) {
        size_t ib = (size_t)c * B_TOTAL + row0;
        float vA = g_val[ib + lane], vB = g_val[ib + lane + 32];
        sx[lane * STRIDE + S1 + c] = vA;
        sx[(lane + 32) * STRIDE + S1 + c] = vB;
    }
    __syncthreads();

    // ---- G5: attn = relu([av(S1)|hx(S2)] @ w_at.T + b_at) -> S0 (K=512 contiguous) ----
    {
#pragma unroll 1
        for (int pass = 0; pass < 4; pass++) {
            int cb = pass * 64 + warp * 8;
            u64 aA[8] = {0,0,0,0,0,0,0,0}, aB[8] = {0,0,0,0,0,0,0,0};
            accum8x2<512>(aA, aB, prow_a + S1, prow_b + S1, p.w_at + (size_t)cb * 512, 512);
#pragma unroll
            for (int j = 0; j < 8; j++) {
                int c = cb + j;
                float b = __ldg(p.b_at + c);
                prow_a[S0 + c] = relu_(red2(aA[j]) + b);
                prow_b[S0 + c] = relu_(red2(aB[j]) + b);
            }
        }
    }
    __syncthreads();

    // ---- G6: pol1(128)->S1[0:128); val1(64)->S1[128:192) ----
    {
#pragma unroll 1
        for (int pass = 0; pass < 2; pass++) {
            int cb = pass * 64 + warp * 8;
            u64 aA[8] = {0,0,0,0,0,0,0,0}, aB[8] = {0,0,0,0,0,0,0,0};
            accum8x2<256>(aA, aB, prow_a + S0, prow_b + S0, p.w_p1 + (size_t)cb * 256, 256);
#pragma unroll
            for (int j = 0; j < 8; j++) {
                float b = __ldg(p.b_p1 + cb + j);
                prow_a[S1 + cb + j] = relu_(red2(aA[j]) + b);
                prow_b[S1 + cb + j] = relu_(red2(aB[j]) + b);
            }
        }
        {
            int cb = warp * 8;
            u64 aA[8] = {0,0,0,0,0,0,0,0}, aB[8] = {0,0,0,0,0,0,0,0};
            accum8x2<256>(aA, aB, prow_a + S0, prow_b + S0, p.w_v1 + (size_t)cb * 256, 256);
#pragma unroll
            for (int j = 0; j < 8; j++) {
                float b = __ldg(p.b_v1 + cb + j);
                prow_a[S1 + 128 + cb + j] = relu_(red2(aA[j]) + b);
                prow_b[S1 + 128 + cb + j] = relu_(red2(aB[j]) + b);
            }
        }
    }
    __syncthreads();

    // ---- G7: pol2(64)->S2[0:64); val2(32)->S2[64:96) ----
    {
        {
            int cb = warp * 8;
            u64 aA[8] = {0,0,0,0,0,0,0,0}, aB[8] = {0,0,0,0,0,0,0,0};
            accum8x2<128>(aA, aB, prow_a + S1, prow_b + S1, p.w_p2 + (size_t)cb * 128, 128);
#pragma unroll
            for (int j = 0; j < 8; j++) {
                float b = __ldg(p.b_p2 + cb + j);
                prow_a[S2 + cb + j] = relu_(red2(aA[j]) + b);
                prow_b[S2 + cb + j] = relu_(red2(aB[j]) + b);
            }
        }
        if (warp < 4) {
            int cb = warp * 8;
            u64 aA[8] = {0,0,0,0,0,0,0,0}, aB[8] = {0,0,0,0,0,0,0,0};
            accum8x2<64>(aA, aB, prow_a + S1 + 128, prow_b + S1 + 128, p.w_v2 + (size_t)cb * 64, 64);
#pragma unroll
            for (int j = 0; j < 8; j++) {
                float b = __ldg(p.b_v2 + cb + j);
                prow_a[S2 + 64 + cb + j] = relu_(red2(aA[j]) + b);
                prow_b[S2 + 64 + cb + j] = relu_(red2(aB[j]) + b);
            }
        }
    }
    __syncthreads();

    // ---- G8: heads. warps 0,1 -> pol rows (lane / lane+32); warps 2,3 -> val ----
    if (warp < 2) {
        int r = lane + (warp & 1) * 32;
        const float* xr = sx + r * STRIDE + S2;
        float a0 = __ldg(p.b_p + 0), a1 = __ldg(p.b_p + 1), a2 = __ldg(p.b_p + 2);
#pragma unroll
        for (int k = 0; k < 64; k++) {
            float x = xr[k];
            a0 = fmaf(x, __ldg(p.w_p + k),       a0);
            a1 = fmaf(x, __ldg(p.w_p + 64 + k),  a1);
            a2 = fmaf(x, __ldg(p.w_p + 128 + k), a2);
        }
        float* po = p.out + OFF_POL + (size_t)(row0 + r) * 3;
        po[0] = a0; po[1] = a1; po[2] = a2;
    } else if (warp < 4) {
        int r = lane + (warp & 1) * 32;
        const float* xr = sx + r * STRIDE + S2 + 64;
        float a = __ldg(p.b_v);
#pragma unroll
        for (int k = 0; k < 32; k++)
            a = fmaf(xr[k], __ldg(p.w_v + k), a);
        p.out[OFF_VAL + row0 + r] = a;
    }
}

extern "C" void kernel_launch(void* const* d_in, const int* in_sizes, int n_in,
                              void* d_out, int out_size) {
    P p;
    p.img   = (const float*)d_in[0];
    p.iidx  = (const int*)  d_in[1];
    p.hx0   = (const float*)d_in[2];
    p.cx0   = (const float*)d_in[3];
    p.query = (const float*)d_in[4];
    p.emb   = (const float*)d_in[5];
    p.w_ta  = (const float*)d_in[6];   p.b_ta = (const float*)d_in[7];
    p.w_ih  = (const float*)d_in[8];   p.w_hh = (const float*)d_in[9];
    p.b_ih  = (const float*)d_in[10];  p.b_hh = (const float*)d_in[11];
    p.w_q   = (const float*)d_in[12];  p.b_q  = (const float*)d_in[13];
    p.w_k   = (const float*)d_in[14];  p.b_k  = (const float*)d_in[15];
    p.w_ba  = (const float*)d_in[16];  p.b_ba = (const float*)d_in[17];
    p.w_at  = (const float*)d_in[18];  p.b_at = (const float*)d_in[19];
    p.w_p1  = (const float*)d_in[20];  p.b_p1 = (const float*)d_in[21];
    p.w_p2  = (const float*)d_in[22];  p.b_p2 = (const float*)d_in[23];
    p.w_p   = (const float*)d_in[24];  p.b_p  = (const float*)d_in[25];
    p.w_v1  = (const float*)d_in[26];  p.b_v1 = (const float*)d_in[27];
    p.w_v2  = (const float*)d_in[28];  p.b_v2 = (const float*)d_in[29];
    p.w_v   = (const float*)d_in[30];  p.b_v  = (const float*)d_in[31];
    p.out   = (float*)d_out;

    size_t smem = (size_t)(M * STRIDE + M * 28) * sizeof(float);  // 204,800 B
    cudaFuncSetAttribute(actor_kernel, cudaFuncAttributeMaxDynamicSharedMemorySize, (int)smem);
    actor_kernel<<<B_TOTAL / M, NTHREADS, smem>>>(p);
}